// round 12
// baseline (speedup 1.0000x reference)
#include <cuda_runtime.h>
#include <cuda_bf16.h>
#include <cstdint>

// ---------------------------------------------------------------------------
// Problem shape (fixed)
// ---------------------------------------------------------------------------
#define B_SZ   4
#define N_DOWN 4096
#define N_UP   16384
#define C_IN   256
#define C_OUT  128
#define KNN    4

#define M_DOWN (B_SZ * N_DOWN)   // 16384
#define M_UP   (B_SZ * N_UP)     // 65536

// Spatial grid: 8x8x8 over [0,1]^3
#define G      8
#define NCELL  (G * G * G)
#define GH     0.125f

// ---------------------------------------------------------------------------
// Helpers
// ---------------------------------------------------------------------------
__device__ __forceinline__ uint32_t smem_u32(const void* p) {
    uint32_t a;
    asm("{ .reg .u64 t; cvta.to.shared.u64 t, %1; cvt.u32.u64 %0, t; }" : "=r"(a) : "l"(p));
    return a;
}

#define LDSM_X4(r0, r1, r2, r3, addr)                                             \
    asm volatile("ldmatrix.sync.aligned.m8n8.x4.shared.b16 {%0,%1,%2,%3}, [%4];"  \
                 : "=r"(r0), "=r"(r1), "=r"(r2), "=r"(r3) : "r"(addr))

__device__ __forceinline__ void mma_bf16(float* c, const uint32_t* a,
                                         uint32_t b0, uint32_t b1) {
    asm volatile(
        "mma.sync.aligned.m16n8k16.row.col.f32.bf16.bf16.f32 "
        "{%0,%1,%2,%3}, {%4,%5,%6,%7}, {%8,%9}, {%0,%1,%2,%3};"
        : "+f"(c[0]), "+f"(c[1]), "+f"(c[2]), "+f"(c[3])
        : "r"(a[0]), "r"(a[1]), "r"(a[2]), "r"(a[3]), "r"(b0), "r"(b1));
}

// monotone key: flip fp32 bits so unsigned compare == float compare
__device__ __forceinline__ uint32_t flip_f32(float f) {
    const uint32_t fb = __float_as_uint(f);
    return (fb & 0x80000000u) ? ~fb : (fb | 0x80000000u);
}
__device__ __forceinline__ float unflip_f32(uint32_t u) {
    return __uint_as_float((u & 0x80000000u) ? (u ^ 0x80000000u) : ~u);
}

__device__ __forceinline__ int cell_of(float px, float py, float pz) {
    const int cx = min(G - 1, (int)(px * (float)G));
    const int cy = min(G - 1, (int)(py * (float)G));
    const int cz = min(G - 1, (int)(pz * (float)G));
    return cx | (cy << 3) | (cz << 6);
}

// ---------------------------------------------------------------------------
// Device-global scratch
// ---------------------------------------------------------------------------
__device__ float g_xd[M_DOWN * C_OUT];              // 8 MB
__device__ int   g_knn_idx[M_UP * KNN];
__device__ float g_knn_w[M_UP * KNN];
__device__ float4         g_pts[B_SZ][N_DOWN];
__device__ uint32_t       g_pid32[B_SZ][N_DOWN];
__device__ int            g_cellstart[B_SZ][NCELL + 1];
__device__ unsigned short g_qid[B_SZ][N_UP];
__device__ int            g_qcellstart[B_SZ][NCELL + 1];
__device__ __nv_bfloat16 g_Wd_hi[C_OUT * C_IN];
__device__ __nv_bfloat16 g_Wd_lo[C_OUT * C_IN];
__device__ __nv_bfloat16 g_Wu_hi[C_OUT * C_OUT];
__device__ __nv_bfloat16 g_Wu_lo[C_OUT * C_OUT];

// ---------------------------------------------------------------------------
// Fused setup: ONE launch, 12 independent blocks @512 threads.
// ---------------------------------------------------------------------------
template <int NPTS, bool WRITE_PTS>
__device__ void build_one_batch(const float* __restrict__ pb, int b)
{
    __shared__ int counts[NCELL];
    __shared__ int s1[NCELL];
    __shared__ int s2[NCELL];

    const int t = threadIdx.x;
    counts[t] = 0;
    __syncthreads();

    for (int j = t; j < NPTS; j += 512)
        atomicAdd(&counts[cell_of(pb[j * 3], pb[j * 3 + 1], pb[j * 3 + 2])], 1);
    __syncthreads();

    s1[t] = counts[t];
    __syncthreads();
    int* src = s1;
    int* dst = s2;
    for (int d = 1; d < NCELL; d <<= 1) {
        int v = src[t];
        if (t >= d) v += src[t - d];
        dst[t] = v;
        __syncthreads();
        int* tmp = src; src = dst; dst = tmp;
    }
    const int excl = src[t] - counts[t];
    if (WRITE_PTS) {
        g_cellstart[b][t] = excl;
        if (t == 0) g_cellstart[b][NCELL] = NPTS;
    } else {
        g_qcellstart[b][t] = excl;
        if (t == 0) g_qcellstart[b][NCELL] = NPTS;
    }
    counts[t] = excl;
    __syncthreads();

    for (int j = t; j < NPTS; j += 512) {
        const float px = pb[j * 3], py = pb[j * 3 + 1], pz = pb[j * 3 + 2];
        const int slot = atomicAdd(&counts[cell_of(px, py, pz)], 1);
        if (WRITE_PTS) {
            const float pp = __fadd_rn(__fadd_rn(__fmul_rn(px, px), __fmul_rn(py, py)),
                                       __fmul_rn(pz, pz));
            g_pts[b][slot]   = make_float4(px, py, pz, pp);
            g_pid32[b][slot] = (uint32_t)j;
        } else {
            g_qid[b][slot] = (unsigned short)j;
        }
    }
}

__global__ void __launch_bounds__(512) setup_kernel(
    const float* __restrict__ p_down,
    const float* __restrict__ p_up,
    const float* __restrict__ W_down,
    const float* __restrict__ W_up)
{
    const int bb = blockIdx.x;
    if (bb < 4) {
        build_one_batch<N_DOWN, true>(p_down + (size_t)bb * N_DOWN * 3, bb);
    } else if (bb < 8) {
        build_one_batch<N_UP, false>(p_up + (size_t)(bb - 4) * N_UP * 3, bb - 4);
    } else {
        for (int idx = (bb - 8) * 512 + threadIdx.x;
             idx < C_OUT * C_IN + C_OUT * C_OUT; idx += 4 * 512) {
            if (idx < C_OUT * C_IN) {
                const int n = idx >> 8;
                const int k = idx & 255;
                const float v = W_down[k * C_OUT + n];
                const __nv_bfloat16 h = __float2bfloat16(v);
                g_Wd_hi[n * C_IN + k] = h;
                g_Wd_lo[n * C_IN + k] = __float2bfloat16(v - __bfloat162float(h));
            } else {
                const int j = idx - C_OUT * C_IN;
                const int n = j >> 7;
                const int k = j & 127;
                const float v = W_up[k * C_OUT + n];
                const __nv_bfloat16 h = __float2bfloat16(v);
                g_Wu_hi[n * C_OUT + k] = h;
                g_Wu_lo[n * C_OUT + k] = __float2bfloat16(v - __bfloat162float(h));
            }
        }
    }
}

// ---------------------------------------------------------------------------
// kNN: one BLOCK per cell, 4 warps each take a 32-query chunk (query-chunk
// parallelism only — every lane still scans ALL candidates, so the per-query
// exit bound stays exact; this was the safe half of the R8 change).
// Dual accumulator banks for ILP; exact merges at vote/output. Shell-cell
// box-distance pruning (margin 1e-5 >> 4e-7 gram-trick error bound).
// u64 key = (flip(d2) << 16) | orig_id == stable jax top_k semantics.
// ---------------------------------------------------------------------------
#define PRUNE_MARGIN 1e-5f

__global__ void __launch_bounds__(128) knn_query(const float* __restrict__ p_up)
{
    const int b    = blockIdx.y;
    const int cell = blockIdx.x;
    const int warp = threadIdx.x >> 5;
    const int lane = threadIdx.x & 31;
    const int cx = cell & 7, cy = (cell >> 3) & 7, cz = cell >> 6;

    const float4*   pts = g_pts[b];
    const uint32_t* pid = g_pid32[b];
    const int*      cst = g_cellstart[b];

    const int qs = g_qcellstart[b][cell];
    const int qe = g_qcellstart[b][cell + 1];

    for (int q0 = qs + warp * 32; q0 < qe; q0 += 128) {
        const int  ql     = q0 + lane;
        const bool active = (ql < qe);
        const int  qid    = (int)g_qid[b][active ? ql : qs];
        const int  r      = b * N_UP + qid;

        const float qx = __ldg(&p_up[(size_t)r * 3 + 0]);
        const float qy = __ldg(&p_up[(size_t)r * 3 + 1]);
        const float qz = __ldg(&p_up[(size_t)r * 3 + 2]);
        const float qq = __fadd_rn(__fadd_rn(__fmul_rn(qx, qx), __fmul_rn(qy, qy)),
                                   __fmul_rn(qz, qz));

        uint64_t a0 = ~0ull, a1 = ~0ull, a2 = ~0ull, a3 = ~0ull;
        uint64_t c0 = ~0ull, c1 = ~0ull, c2 = ~0ull, c3 = ~0ull;

        #define INSERT4(K0, K1, K2, K3, key_)                                       \
        {                                                                           \
            const bool p0_ = key_ < K0, p1_ = key_ < K1;                            \
            const bool p2_ = key_ < K2, p3_ = key_ < K3;                            \
            K3 = p3_ ? (p2_ ? K2 : key_) : K3;                                      \
            K2 = p2_ ? (p1_ ? K1 : key_) : K2;                                      \
            K1 = p1_ ? (p0_ ? K0 : key_) : K1;                                      \
            K0 = p0_ ? key_ : K0;                                                   \
        }

        #define MAKE_KEY(j_, key_)                                                  \
            uint64_t key_;                                                          \
            {                                                                       \
                const float4 p_ = __ldg(&pts[j_]);                                  \
                const uint32_t oid_ = __ldg(&pid[j_]);                              \
                float dot_ = __fmul_rn(qx, p_.x);                                   \
                dot_ = fmaf(qy, p_.y, dot_);                                        \
                dot_ = fmaf(qz, p_.z, dot_);                                        \
                const float d2_ = __fadd_rn(__fadd_rn(qq, p_.w),                    \
                                            -__fmul_rn(2.0f, dot_));                \
                key_ = ((uint64_t)flip_f32(d2_) << 16) | oid_;                      \
            }

        #define SCAN_CELL(c)                                                        \
        {                                                                           \
            const int e_ = __ldg(&cst[(c) + 1]);                                    \
            int j_ = __ldg(&cst[(c)]);                                              \
            for (; j_ + 1 < e_; j_ += 2) {                                          \
                MAKE_KEY(j_,     keyA_);                                            \
                MAKE_KEY(j_ + 1, keyB_);                                            \
                INSERT4(a0, a1, a2, a3, keyA_);                                     \
                INSERT4(c0, c1, c2, c3, keyB_);                                     \
            }                                                                       \
            if (j_ < e_) {                                                          \
                MAKE_KEY(j_, keyA_);                                                \
                INSERT4(a0, a1, a2, a3, keyA_);                                     \
            }                                                                       \
        }

        // Chebyshev <= 1 cube (always scanned)
        {
            const int z0 = max(0, cz - 1), z1 = min(G - 1, cz + 1);
            const int y0 = max(0, cy - 1), y1 = min(G - 1, cy + 1);
            const int x0 = max(0, cx - 1), x1 = min(G - 1, cx + 1);
            for (int z = z0; z <= z1; z++)
                for (int y = y0; y <= y1; y++)
                    for (int x = x0; x <= x1; x++)
                        SCAN_CELL(x | (y << 3) | (z << 6));
        }

        // expanding shells with merged bound + per-cell box pruning
        for (int rad = 2; rad < G; rad++) {
            uint64_t t0 = a0, t1 = a1, t2 = a2, t3 = a3;
            INSERT4(t0, t1, t2, t3, c0);
            INSERT4(t0, t1, t2, t3, c1);
            INSERT4(t0, t1, t2, t3, c2);
            INSERT4(t0, t1, t2, t3, c3);
            const float bd3v = unflip_f32((uint32_t)(t3 >> 16));

            const float dmin = (float)(rad - 1) * GH;
            const bool  done = !active || (bd3v <= dmin * dmin);
            if (__all_sync(0xffffffffu, done)) break;

            const float thresh = bd3v + PRUNE_MARGIN;

            const int z0 = max(0, cz - rad), z1 = min(G - 1, cz + rad);
            const int y0 = max(0, cy - rad), y1 = min(G - 1, cy + rad);
            const int x0 = max(0, cx - rad), x1 = min(G - 1, cx + rad);
            for (int z = z0; z <= z1; z++) {
                const int az = abs(z - cz);
                const float bz0 = z * GH, bz1 = bz0 + GH;
                const float ddz = fmaxf(0.0f, fmaxf(bz0 - qz, qz - bz1));
                for (int y = y0; y <= y1; y++) {
                    const int ay = abs(y - cy);
                    const float by0 = y * GH, by1 = by0 + GH;
                    const float ddy = fmaxf(0.0f, fmaxf(by0 - qy, qy - by1));
                    for (int x = x0; x <= x1; x++) {
                        const int ax = abs(x - cx);
                        if (max(ax, max(ay, az)) != rad) continue;
                        const float bx0 = x * GH, bx1 = bx0 + GH;
                        const float ddx = fmaxf(0.0f, fmaxf(bx0 - qx, qx - bx1));
                        const float cd2 = ddx * ddx + ddy * ddy + ddz * ddz;
                        const bool need = !done && (cd2 < thresh);
                        if (__any_sync(0xffffffffu, need))
                            SCAN_CELL(x | (y << 3) | (z << 6));
                    }
                }
            }
        }
        #undef SCAN_CELL
        #undef MAKE_KEY

        INSERT4(a0, a1, a2, a3, c0);
        INSERT4(a0, a1, a2, a3, c1);
        INSERT4(a0, a1, a2, a3, c2);
        INSERT4(a0, a1, a2, a3, c3);
        #undef INSERT4

        if (active) {
            const float d0  = unflip_f32((uint32_t)(a0 >> 16));
            const float d1  = unflip_f32((uint32_t)(a1 >> 16));
            const float d2v = unflip_f32((uint32_t)(a2 >> 16));
            const float d3  = unflip_f32((uint32_t)(a3 >> 16));
            const float w0 = 1.0f / fmaxf(d0, 1e-16f);
            const float w1 = 1.0f / fmaxf(d1, 1e-16f);
            const float w2 = 1.0f / fmaxf(d2v, 1e-16f);
            const float w3 = 1.0f / fmaxf(d3, 1e-16f);
            const float inv = 1.0f / (((w0 + w1) + w2) + w3);
            g_knn_idx[r * 4 + 0] = (int)(a0 & 0xFFFFu);
            g_knn_idx[r * 4 + 1] = (int)(a1 & 0xFFFFu);
            g_knn_idx[r * 4 + 2] = (int)(a2 & 0xFFFFu);
            g_knn_idx[r * 4 + 3] = (int)(a3 & 0xFFFFu);
            g_knn_w[r * 4 + 0] = w0 * inv;
            g_knn_w[r * 4 + 1] = w1 * inv;
            g_knn_w[r * 4 + 2] = w2 * inv;
            g_knn_w[r * 4 + 3] = w3 * inv;
        }
    }
}

// ---------------------------------------------------------------------------
// Down-GEMM (unchanged, passing): mma.sync bf16 hi/lo split, 128x128, BK=32.
// ---------------------------------------------------------------------------
#define ROWB 80   // smem row pitch (32 bf16 = 64 B data + 16 B pad)

__global__ void __launch_bounds__(256) gemm_down(
    const float* __restrict__ A,
    const __nv_bfloat16* __restrict__ Whi,
    const __nv_bfloat16* __restrict__ Wlo,
    const float* __restrict__ bias,
    const float* __restrict__ gamma,
    const float* __restrict__ beta,
    const float* __restrict__ mean,
    const float* __restrict__ var)
{
    constexpr int KDIM = C_IN;
    __shared__ __align__(16) uint8_t sAh[128 * ROWB];
    __shared__ __align__(16) uint8_t sAl[128 * ROWB];
    __shared__ __align__(16) uint8_t sBh[128 * ROWB];
    __shared__ __align__(16) uint8_t sBl[128 * ROWB];
    __shared__ float scale_s[C_OUT];
    __shared__ float shift_s[C_OUT];

    const int tid  = threadIdx.x;
    const int wid  = tid >> 5;
    const int lane = tid & 31;
    const int wm   = wid & 3;
    const int wn   = wid >> 2;
    const int row0 = blockIdx.x * 128;

    if (tid < C_OUT) {
        const float s = gamma[tid] * rsqrtf(var[tid] + 1e-5f);
        scale_s[tid] = s;
        shift_s[tid] = beta[tid] + (bias[tid] - mean[tid]) * s;
    }

    float acc[2][8][4];
    #pragma unroll
    for (int mt = 0; mt < 2; mt++)
        #pragma unroll
        for (int nt = 0; nt < 8; nt++)
            #pragma unroll
            for (int c = 0; c < 4; c++) acc[mt][nt][c] = 0.0f;

    const uint32_t sAh_b = smem_u32(sAh), sAl_b = smem_u32(sAl);
    const uint32_t sBh_b = smem_u32(sBh), sBl_b = smem_u32(sBl);
    const int a_row  = wm * 32 + (lane & 7) + ((lane >> 3) & 1) * 8;
    const int a_kby  = ((lane >> 4) & 1) * 16;
    const int b_nrow = wn * 64 + (lane & 7) + ((lane >> 4) & 1) * 8;
    const int b_kby  = ((lane >> 3) & 1) * 16;

    const int rr   = tid >> 1;
    const int half = tid & 1;

    for (int kc = 0; kc < KDIM / 32; kc++) {
        const int kt = kc * 32;
        {
            const float* ap = A + (size_t)(row0 + rr) * KDIM + kt + half * 16;
            const uint32_t wb = rr * ROWB + half * 32;
            #pragma unroll
            for (int q = 0; q < 2; q++) {
                const float4 v0 = *(const float4*)(ap + q * 8);
                const float4 v1 = *(const float4*)(ap + q * 8 + 4);
                __nv_bfloat162 h0 = __floats2bfloat162_rn(v0.x, v0.y);
                __nv_bfloat162 h1 = __floats2bfloat162_rn(v0.z, v0.w);
                __nv_bfloat162 h2 = __floats2bfloat162_rn(v1.x, v1.y);
                __nv_bfloat162 h3 = __floats2bfloat162_rn(v1.z, v1.w);
                __nv_bfloat162 l0 = __floats2bfloat162_rn(v0.x - __bfloat162float(h0.x),
                                                          v0.y - __bfloat162float(h0.y));
                __nv_bfloat162 l1 = __floats2bfloat162_rn(v0.z - __bfloat162float(h1.x),
                                                          v0.w - __bfloat162float(h1.y));
                __nv_bfloat162 l2 = __floats2bfloat162_rn(v1.x - __bfloat162float(h2.x),
                                                          v1.y - __bfloat162float(h2.y));
                __nv_bfloat162 l3 = __floats2bfloat162_rn(v1.z - __bfloat162float(h3.x),
                                                          v1.w - __bfloat162float(h3.y));
                *(uint4*)(sAh + wb + q * 16) = make_uint4(
                    *(uint32_t*)&h0, *(uint32_t*)&h1, *(uint32_t*)&h2, *(uint32_t*)&h3);
                *(uint4*)(sAl + wb + q * 16) = make_uint4(
                    *(uint32_t*)&l0, *(uint32_t*)&l1, *(uint32_t*)&l2, *(uint32_t*)&l3);
            }
        }
        {
            const __nv_bfloat16* wh = Whi + (size_t)rr * KDIM + kt + half * 16;
            const __nv_bfloat16* wl = Wlo + (size_t)rr * KDIM + kt + half * 16;
            const uint32_t wb = rr * ROWB + half * 32;
            *(uint4*)(sBh + wb)      = *(const uint4*)(wh);
            *(uint4*)(sBh + wb + 16) = *(const uint4*)(wh + 8);
            *(uint4*)(sBl + wb)      = *(const uint4*)(wl);
            *(uint4*)(sBl + wb + 16) = *(const uint4*)(wl + 8);
        }
        __syncthreads();

        #pragma unroll
        for (int kk = 0; kk < 32; kk += 16) {
            uint32_t ah[2][4], al[2][4];
            #pragma unroll
            for (int mt = 0; mt < 2; mt++) {
                const uint32_t ao = (uint32_t)((a_row + mt * 16) * ROWB + kk * 2 + a_kby);
                LDSM_X4(ah[mt][0], ah[mt][1], ah[mt][2], ah[mt][3], sAh_b + ao);
                LDSM_X4(al[mt][0], al[mt][1], al[mt][2], al[mt][3], sAl_b + ao);
            }
            #pragma unroll
            for (int ntp = 0; ntp < 4; ntp++) {
                const uint32_t bo = (uint32_t)((b_nrow + ntp * 16) * ROWB + kk * 2 + b_kby);
                uint32_t bh0, bh1, bh2, bh3, bl0, bl1, bl2, bl3;
                LDSM_X4(bh0, bh1, bh2, bh3, sBh_b + bo);
                LDSM_X4(bl0, bl1, bl2, bl3, sBl_b + bo);
                #pragma unroll
                for (int mt = 0; mt < 2; mt++) {
                    mma_bf16(acc[mt][ntp * 2 + 0], ah[mt], bh0, bh1);
                    mma_bf16(acc[mt][ntp * 2 + 0], al[mt], bh0, bh1);
                    mma_bf16(acc[mt][ntp * 2 + 1], ah[mt], bh2, bh3);
                    mma_bf16(acc[mt][ntp * 2 + 1], al[mt], bh2, bh3);
                    mma_bf16(acc[mt][ntp * 2 + 0], ah[mt], bl0, bl1);
                    mma_bf16(acc[mt][ntp * 2 + 1], ah[mt], bl2, bl3);
                }
            }
        }
        __syncthreads();
    }

    const int quad = lane >> 2;
    const int tq2  = (lane & 3) * 2;
    #pragma unroll
    for (int mt = 0; mt < 2; mt++) {
        #pragma unroll
        for (int h = 0; h < 2; h++) {
            const int r = row0 + wm * 32 + mt * 16 + quad + h * 8;
            #pragma unroll
            for (int nt = 0; nt < 8; nt++) {
                const int col = wn * 64 + nt * 8 + tq2;
                float o0 = fmaxf(fmaf(acc[mt][nt][h * 2 + 0], scale_s[col],     shift_s[col]),     0.0f);
                float o1 = fmaxf(fmaf(acc[mt][nt][h * 2 + 1], scale_s[col + 1], shift_s[col + 1]), 0.0f);
                *(float2*)(g_xd + (size_t)r * C_OUT + col) = make_float2(o0, o1);
            }
        }
    }
}

// ---------------------------------------------------------------------------
// Up-GEMM (K=128): B hi/lo fully smem-resident (loaded once, 80 KB as 4
// chunk-tiles); A register-prefetched + single smem buffer. Dynamic smem
// ~101 KB -> 2 CTAs/SM. Epilogue fuses BN/ReLU + kNN gather + add.
// ---------------------------------------------------------------------------
#define ACHUNK (128 * ROWB)             // 10240 B per chunk-tile
#define OFF_BH 0
#define OFF_BL (4 * ACHUNK)             // 40960
#define OFF_AH (8 * ACHUNK)             // 81920
#define OFF_AL (9 * ACHUNK)             // 92160
#define OFF_SC (10 * ACHUNK)            // 102400
#define OFF_SH (10 * ACHUNK + 512)
#define SMEM_UP (10 * ACHUNK + 1024)    // 103424 B

__global__ void __launch_bounds__(256, 2) gemm_up(
    const float* __restrict__ A,
    const __nv_bfloat16* __restrict__ Whi,
    const __nv_bfloat16* __restrict__ Wlo,
    const float* __restrict__ bias,
    const float* __restrict__ gamma,
    const float* __restrict__ beta,
    const float* __restrict__ mean,
    const float* __restrict__ var,
    float* __restrict__ outp)
{
    constexpr int KDIM = C_OUT;          // 128
    extern __shared__ __align__(16) uint8_t sm[];
    float* scale_s = (float*)(sm + OFF_SC);
    float* shift_s = (float*)(sm + OFF_SH);

    const int tid  = threadIdx.x;
    const int wid  = tid >> 5;
    const int lane = tid & 31;
    const int wm   = wid & 3;
    const int wn   = wid >> 2;
    const int row0 = blockIdx.x * 128;

    if (tid < C_OUT) {
        const float s = gamma[tid] * rsqrtf(var[tid] + 1e-5f);
        scale_s[tid] = s;
        shift_s[tid] = beta[tid] + (bias[tid] - mean[tid]) * s;
    }

    const int rr   = tid >> 1;
    const int half = tid & 1;

    // ---- B preload: all 4 K-chunks, hi & lo (once) ----
    #pragma unroll
    for (int c = 0; c < 4; c++) {
        const __nv_bfloat16* wh = Whi + (size_t)rr * KDIM + c * 32 + half * 16;
        const __nv_bfloat16* wl = Wlo + (size_t)rr * KDIM + c * 32 + half * 16;
        const uint32_t wb = c * ACHUNK + rr * ROWB + half * 32;
        *(uint4*)(sm + OFF_BH + wb)      = *(const uint4*)(wh);
        *(uint4*)(sm + OFF_BH + wb + 16) = *(const uint4*)(wh + 8);
        *(uint4*)(sm + OFF_BL + wb)      = *(const uint4*)(wl);
        *(uint4*)(sm + OFF_BL + wb + 16) = *(const uint4*)(wl + 8);
    }

    float acc[2][8][4];
    #pragma unroll
    for (int mt = 0; mt < 2; mt++)
        #pragma unroll
        for (int nt = 0; nt < 8; nt++)
            #pragma unroll
            for (int c = 0; c < 4; c++) acc[mt][nt][c] = 0.0f;

    const uint32_t sAh_b = smem_u32(sm + OFF_AH);
    const uint32_t sAl_b = smem_u32(sm + OFF_AL);
    const uint32_t sBh_b = smem_u32(sm + OFF_BH);
    const uint32_t sBl_b = smem_u32(sm + OFF_BL);
    const int a_row  = wm * 32 + (lane & 7) + ((lane >> 3) & 1) * 8;
    const int a_kby  = ((lane >> 4) & 1) * 16;
    const int b_nrow = wn * 64 + (lane & 7) + ((lane >> 4) & 1) * 8;
    const int b_kby  = ((lane >> 3) & 1) * 16;
    const uint32_t awb = rr * ROWB + half * 32;

    #define LOAD_A_REGS(c_, v_)                                                   \
    {                                                                             \
        const float* ap_ = A + (size_t)(row0 + rr) * KDIM + (c_) * 32 + half * 16;\
        v_[0] = *(const float4*)(ap_);                                            \
        v_[1] = *(const float4*)(ap_ + 4);                                        \
        v_[2] = *(const float4*)(ap_ + 8);                                        \
        v_[3] = *(const float4*)(ap_ + 12);                                       \
    }
    #define CONVERT_STS(v_)                                                       \
    {                                                                             \
        _Pragma("unroll")                                                         \
        for (int q_ = 0; q_ < 2; q_++) {                                          \
            const float4 v0_ = v_[q_ * 2];                                        \
            const float4 v1_ = v_[q_ * 2 + 1];                                    \
            __nv_bfloat162 h0_ = __floats2bfloat162_rn(v0_.x, v0_.y);             \
            __nv_bfloat162 h1_ = __floats2bfloat162_rn(v0_.z, v0_.w);             \
            __nv_bfloat162 h2_ = __floats2bfloat162_rn(v1_.x, v1_.y);             \
            __nv_bfloat162 h3_ = __floats2bfloat162_rn(v1_.z, v1_.w);             \
            __nv_bfloat162 l0_ = __floats2bfloat162_rn(v0_.x - __bfloat162float(h0_.x), \
                                                       v0_.y - __bfloat162float(h0_.y)); \
            __nv_bfloat162 l1_ = __floats2bfloat162_rn(v0_.z - __bfloat162float(h1_.x), \
                                                       v0_.w - __bfloat162float(h1_.y)); \
            __nv_bfloat162 l2_ = __floats2bfloat162_rn(v1_.x - __bfloat162float(h2_.x), \
                                                       v1_.y - __bfloat162float(h2_.y)); \
            __nv_bfloat162 l3_ = __floats2bfloat162_rn(v1_.z - __bfloat162float(h3_.x), \
                                                       v1_.w - __bfloat162float(h3_.y)); \
            *(uint4*)(sm + OFF_AH + awb + q_ * 16) = make_uint4(                  \
                *(uint32_t*)&h0_, *(uint32_t*)&h1_, *(uint32_t*)&h2_, *(uint32_t*)&h3_); \
            *(uint4*)(sm + OFF_AL + awb + q_ * 16) = make_uint4(                  \
                *(uint32_t*)&l0_, *(uint32_t*)&l1_, *(uint32_t*)&l2_, *(uint32_t*)&l3_); \
        }                                                                         \
    }

    // prologue: chunk 0 into smem
    {
        float4 v[4];
        LOAD_A_REGS(0, v);
        CONVERT_STS(v);
    }
    __syncthreads();

    #pragma unroll
    for (int kc = 0; kc < 4; kc++) {
        float4 nv[4];
        if (kc < 3) LOAD_A_REGS(kc + 1, nv);     // prefetch overlaps MMAs

        #pragma unroll
        for (int kk = 0; kk < 32; kk += 16) {
            uint32_t ah[2][4], al[2][4];
            #pragma unroll
            for (int mt = 0; mt < 2; mt++) {
                const uint32_t ao = (uint32_t)((a_row + mt * 16) * ROWB + kk * 2 + a_kby);
                LDSM_X4(ah[mt][0], ah[mt][1], ah[mt][2], ah[mt][3], sAh_b + ao);
                LDSM_X4(al[mt][0], al[mt][1], al[mt][2], al[mt][3], sAl_b + ao);
            }
            const uint32_t bchunk = kc * ACHUNK;
            #pragma unroll
            for (int ntp = 0; ntp < 4; ntp++) {
                const uint32_t bo = bchunk
                    + (uint32_t)((b_nrow + ntp * 16) * ROWB + kk * 2 + b_kby);
                uint32_t bh0, bh1, bh2, bh3, bl0, bl1, bl2, bl3;
                LDSM_X4(bh0, bh1, bh2, bh3, sBh_b + bo);
                LDSM_X4(bl0, bl1, bl2, bl3, sBl_b + bo);
                #pragma unroll
                for (int mt = 0; mt < 2; mt++) {
                    mma_bf16(acc[mt][ntp * 2 + 0], ah[mt], bh0, bh1);
                    mma_bf16(acc[mt][ntp * 2 + 0], al[mt], bh0, bh1);
                    mma_bf16(acc[mt][ntp * 2 + 1], ah[mt], bh2, bh3);
                    mma_bf16(acc[mt][ntp * 2 + 1], al[mt], bh2, bh3);
                    mma_bf16(acc[mt][ntp * 2 + 0], ah[mt], bl0, bl1);
                    mma_bf16(acc[mt][ntp * 2 + 1], ah[mt], bl2, bl3);
                }
            }
        }

        if (kc < 3) {
            __syncthreads();        // all reads of A tile done (WAR)
            CONVERT_STS(nv);
            __syncthreads();        // A tile ready
        }
    }
    #undef LOAD_A_REGS
    #undef CONVERT_STS

    // ---- epilogue: BN + ReLU + kNN gather + add ----
    const int quad = lane >> 2;
    const int tq2  = (lane & 3) * 2;
    #pragma unroll
    for (int mt = 0; mt < 2; mt++) {
        #pragma unroll
        for (int h = 0; h < 2; h++) {
            const int r = row0 + wm * 32 + mt * 16 + quad + h * 8;
            const int bidx = r >> 14;
            const float* xdb = g_xd + (size_t)bidx * N_DOWN * C_OUT;
            const float* fr[KNN];
            float wk[KNN];
            #pragma unroll
            for (int k = 0; k < KNN; k++) {
                fr[k] = xdb + (size_t)g_knn_idx[r * 4 + k] * C_OUT;
                wk[k] = g_knn_w[r * 4 + k];
            }
            #pragma unroll
            for (int nt = 0; nt < 8; nt++) {
                const int col = wn * 64 + nt * 8 + tq2;
                float o0 = fmaxf(fmaf(acc[mt][nt][h * 2 + 0], scale_s[col],     shift_s[col]),     0.0f);
                float o1 = fmaxf(fmaf(acc[mt][nt][h * 2 + 1], scale_s[col + 1], shift_s[col + 1]), 0.0f);
                #pragma unroll
                for (int k = 0; k < KNN; k++) {
                    const float2 v = *(const float2*)(fr[k] + col);
                    o0 = fmaf(wk[k], v.x, o0);
                    o1 = fmaf(wk[k], v.y, o1);
                }
                *(float2*)(outp + (size_t)r * C_OUT + col) = make_float2(o0, o1);
            }
        }
    }
}

// ---------------------------------------------------------------------------
// Launch: fork-join stream overlap (kNN || down-GEMM), graph-capturable.
// ---------------------------------------------------------------------------
extern "C" void kernel_launch(void* const* d_in, const int* in_sizes, int n_in,
                              void* d_out, int out_size)
{
    const float* x_down  = (const float*)d_in[0];
    const float* x_up    = (const float*)d_in[1];
    const float* p_down  = (const float*)d_in[2];
    const float* p_up    = (const float*)d_in[3];
    const float* W_down  = (const float*)d_in[4];
    const float* b_down  = (const float*)d_in[5];
    const float* g_down  = (const float*)d_in[6];
    const float* be_down = (const float*)d_in[7];
    const float* m_down  = (const float*)d_in[8];
    const float* v_down  = (const float*)d_in[9];
    const float* W_up    = (const float*)d_in[10];
    const float* b_up    = (const float*)d_in[11];
    const float* g_up    = (const float*)d_in[12];
    const float* be_up   = (const float*)d_in[13];
    const float* m_up    = (const float*)d_in[14];
    const float* v_up    = (const float*)d_in[15];
    float* out = (float*)d_out;

    __nv_bfloat16 *wdh, *wdl, *wuh, *wul;
    cudaGetSymbolAddress((void**)&wdh, g_Wd_hi);
    cudaGetSymbolAddress((void**)&wdl, g_Wd_lo);
    cudaGetSymbolAddress((void**)&wuh, g_Wu_hi);
    cudaGetSymbolAddress((void**)&wul, g_Wu_lo);

    static cudaStream_t s_knn = nullptr;
    static cudaEvent_t  ev_setup = nullptr, ev_knn = nullptr;
    if (s_knn == nullptr) {
        cudaStreamCreateWithFlags(&s_knn, cudaStreamNonBlocking);
        cudaEventCreateWithFlags(&ev_setup, cudaEventDisableTiming);
        cudaEventCreateWithFlags(&ev_knn,   cudaEventDisableTiming);
        cudaFuncSetAttribute(gemm_up, cudaFuncAttributeMaxDynamicSharedMemorySize, SMEM_UP);
    }

    // 1) fused setup on the main (capture) stream
    setup_kernel<<<12, 512>>>(p_down, p_up, W_down, W_up);
    cudaEventRecord(ev_setup, 0);

    // 2) kNN on side stream, concurrent with down-GEMM on main stream
    cudaStreamWaitEvent(s_knn, ev_setup, 0);
    dim3 qgrid(NCELL, B_SZ);
    knn_query<<<qgrid, 128, 0, s_knn>>>(p_up);
    cudaEventRecord(ev_knn, s_knn);

    // 3) down MLP -> g_xd (main stream, overlaps kNN)
    gemm_down<<<M_DOWN / 128, 256>>>(
        x_down, wdh, wdl, b_down, g_down, be_down, m_down, v_down);

    // 4) join, then up MLP + gather + add -> out
    cudaStreamWaitEvent(0, ev_knn, 0);
    gemm_up<<<M_UP / 128, 256, SMEM_UP>>>(
        x_up, wuh, wul, b_up, g_up, be_up, m_up, v_up, out);
}

// round 13
// speedup vs baseline: 1.0827x; 1.0827x over previous
#include <cuda_runtime.h>
#include <cuda_bf16.h>
#include <cstdint>

// ---------------------------------------------------------------------------
// Problem shape (fixed)
// ---------------------------------------------------------------------------
#define B_SZ   4
#define N_DOWN 4096
#define N_UP   16384
#define C_IN   256
#define C_OUT  128
#define KNN    4

#define M_DOWN (B_SZ * N_DOWN)   // 16384
#define M_UP   (B_SZ * N_UP)     // 65536

// Spatial grid: 8x8x8 over [0,1]^3
#define G      8
#define NCELL  (G * G * G)
#define GH     0.125f

// ---------------------------------------------------------------------------
// Helpers
// ---------------------------------------------------------------------------
__device__ __forceinline__ uint32_t smem_u32(const void* p) {
    uint32_t a;
    asm("{ .reg .u64 t; cvta.to.shared.u64 t, %1; cvt.u32.u64 %0, t; }" : "=r"(a) : "l"(p));
    return a;
}

#define LDSM_X4(r0, r1, r2, r3, addr)                                             \
    asm volatile("ldmatrix.sync.aligned.m8n8.x4.shared.b16 {%0,%1,%2,%3}, [%4];"  \
                 : "=r"(r0), "=r"(r1), "=r"(r2), "=r"(r3) : "r"(addr))

__device__ __forceinline__ void mma_bf16(float* c, const uint32_t* a,
                                         uint32_t b0, uint32_t b1) {
    asm volatile(
        "mma.sync.aligned.m16n8k16.row.col.f32.bf16.bf16.f32 "
        "{%0,%1,%2,%3}, {%4,%5,%6,%7}, {%8,%9}, {%0,%1,%2,%3};"
        : "+f"(c[0]), "+f"(c[1]), "+f"(c[2]), "+f"(c[3])
        : "r"(a[0]), "r"(a[1]), "r"(a[2]), "r"(a[3]), "r"(b0), "r"(b1));
}

// monotone key: flip fp32 bits so unsigned compare == float compare
__device__ __forceinline__ uint32_t flip_f32(float f) {
    const uint32_t fb = __float_as_uint(f);
    return (fb & 0x80000000u) ? ~fb : (fb | 0x80000000u);
}
__device__ __forceinline__ float unflip_f32(uint32_t u) {
    return __uint_as_float((u & 0x80000000u) ? (u ^ 0x80000000u) : ~u);
}

__device__ __forceinline__ int cell_of(float px, float py, float pz) {
    const int cx = min(G - 1, (int)(px * (float)G));
    const int cy = min(G - 1, (int)(py * (float)G));
    const int cz = min(G - 1, (int)(pz * (float)G));
    return cx | (cy << 3) | (cz << 6);
}

// ---------------------------------------------------------------------------
// Device-global scratch
// ---------------------------------------------------------------------------
__device__ float g_xd[M_DOWN * C_OUT];              // 8 MB
__device__ int   g_knn_idx[M_UP * KNN];
__device__ float g_knn_w[M_UP * KNN];
__device__ float4         g_pts[B_SZ][N_DOWN];
__device__ uint32_t       g_pid32[B_SZ][N_DOWN];
__device__ int            g_cellstart[B_SZ][NCELL + 1];
__device__ unsigned short g_qid[B_SZ][N_UP];
__device__ int            g_qcellstart[B_SZ][NCELL + 1];
__device__ __nv_bfloat16 g_Wd_hi[C_OUT * C_IN];
__device__ __nv_bfloat16 g_Wd_lo[C_OUT * C_IN];
__device__ __nv_bfloat16 g_Wu_hi[C_OUT * C_OUT];
__device__ __nv_bfloat16 g_Wu_lo[C_OUT * C_OUT];

// ---------------------------------------------------------------------------
// Fused setup: ONE launch, 12 independent blocks @512 threads.
// ---------------------------------------------------------------------------
template <int NPTS, bool WRITE_PTS>
__device__ void build_one_batch(const float* __restrict__ pb, int b)
{
    __shared__ int counts[NCELL];
    __shared__ int s1[NCELL];
    __shared__ int s2[NCELL];

    const int t = threadIdx.x;
    counts[t] = 0;
    __syncthreads();

    for (int j = t; j < NPTS; j += 512)
        atomicAdd(&counts[cell_of(pb[j * 3], pb[j * 3 + 1], pb[j * 3 + 2])], 1);
    __syncthreads();

    s1[t] = counts[t];
    __syncthreads();
    int* src = s1;
    int* dst = s2;
    for (int d = 1; d < NCELL; d <<= 1) {
        int v = src[t];
        if (t >= d) v += src[t - d];
        dst[t] = v;
        __syncthreads();
        int* tmp = src; src = dst; dst = tmp;
    }
    const int excl = src[t] - counts[t];
    if (WRITE_PTS) {
        g_cellstart[b][t] = excl;
        if (t == 0) g_cellstart[b][NCELL] = NPTS;
    } else {
        g_qcellstart[b][t] = excl;
        if (t == 0) g_qcellstart[b][NCELL] = NPTS;
    }
    counts[t] = excl;
    __syncthreads();

    for (int j = t; j < NPTS; j += 512) {
        const float px = pb[j * 3], py = pb[j * 3 + 1], pz = pb[j * 3 + 2];
        const int slot = atomicAdd(&counts[cell_of(px, py, pz)], 1);
        if (WRITE_PTS) {
            const float pp = __fadd_rn(__fadd_rn(__fmul_rn(px, px), __fmul_rn(py, py)),
                                       __fmul_rn(pz, pz));
            g_pts[b][slot]   = make_float4(px, py, pz, pp);
            g_pid32[b][slot] = (uint32_t)j;
        } else {
            g_qid[b][slot] = (unsigned short)j;
        }
    }
}

__global__ void __launch_bounds__(512) setup_kernel(
    const float* __restrict__ p_down,
    const float* __restrict__ p_up,
    const float* __restrict__ W_down,
    const float* __restrict__ W_up)
{
    const int bb = blockIdx.x;
    if (bb < 4) {
        build_one_batch<N_DOWN, true>(p_down + (size_t)bb * N_DOWN * 3, bb);
    } else if (bb < 8) {
        build_one_batch<N_UP, false>(p_up + (size_t)(bb - 4) * N_UP * 3, bb - 4);
    } else {
        for (int idx = (bb - 8) * 512 + threadIdx.x;
             idx < C_OUT * C_IN + C_OUT * C_OUT; idx += 4 * 512) {
            if (idx < C_OUT * C_IN) {
                const int n = idx >> 8;
                const int k = idx & 255;
                const float v = W_down[k * C_OUT + n];
                const __nv_bfloat16 h = __float2bfloat16(v);
                g_Wd_hi[n * C_IN + k] = h;
                g_Wd_lo[n * C_IN + k] = __float2bfloat16(v - __bfloat162float(h));
            } else {
                const int j = idx - C_OUT * C_IN;
                const int n = j >> 7;
                const int k = j & 127;
                const float v = W_up[k * C_OUT + n];
                const __nv_bfloat16 h = __float2bfloat16(v);
                g_Wu_hi[n * C_OUT + k] = h;
                g_Wu_lo[n * C_OUT + k] = __float2bfloat16(v - __bfloat162float(h));
            }
        }
    }
}

// ---------------------------------------------------------------------------
// kNN: one BLOCK per cell. The <=27-cell Chebyshev-1 cube (~216 pts) is
// STAGED INTO SHARED MEMORY once, then 4 warps (32-query chunks each) scan
// it via broadcast LDS — full reuse, no dependent-LDG chains. Shells rad>=2
// (rarely reached: typical bd3 ~ 3.8e-3 < GH^2) use the pruned global path.
// Candidate set, key semantics, arithmetic all identical to the passing
// version -> rel_err unchanged.
// u64 key = (flip(d2) << 16) | orig_id == stable jax top_k semantics.
// ---------------------------------------------------------------------------
#define PRUNE_MARGIN 1e-5f
#define STAGE_CAP    1024

__global__ void __launch_bounds__(128) knn_query(const float* __restrict__ p_up)
{
    __shared__ float4         spts[STAGE_CAP];
    __shared__ unsigned short ssid[STAGE_CAP];

    const int b    = blockIdx.y;
    const int cell = blockIdx.x;
    const int warp = threadIdx.x >> 5;
    const int lane = threadIdx.x & 31;
    const int tid  = threadIdx.x;
    const int cx = cell & 7, cy = (cell >> 3) & 7, cz = cell >> 6;

    const float4*   pts = g_pts[b];
    const uint32_t* pid = g_pid32[b];
    const int*      cst = g_cellstart[b];

    // cube bounds
    const int z0c = max(0, cz - 1), z1c = min(G - 1, cz + 1);
    const int y0c = max(0, cy - 1), y1c = min(G - 1, cy + 1);
    const int x0c = max(0, cx - 1), x1c = min(G - 1, cx + 1);

    // stage the cube into smem (no syncs inside; loads pipeline)
    int base = 0;
    for (int z = z0c; z <= z1c; z++)
        for (int y = y0c; y <= y1c; y++)
            for (int x = x0c; x <= x1c; x++) {
                const int c = x | (y << 3) | (z << 6);
                const int s = __ldg(&cst[c]);
                const int e = __ldg(&cst[c + 1]);
                const int len = e - s;
                if (base + len <= STAGE_CAP) {
                    for (int i = tid; i < len; i += 128) {
                        spts[base + i] = __ldg(&pts[s + i]);
                        ssid[base + i] = (unsigned short)__ldg(&pid[s + i]);
                    }
                }
                base += len;
            }
    const bool staged = (base <= STAGE_CAP);
    const int  total  = base;
    __syncthreads();

    const int qs = g_qcellstart[b][cell];
    const int qe = g_qcellstart[b][cell + 1];

    for (int q0 = qs + warp * 32; q0 < qe; q0 += 128) {
        const int  ql     = q0 + lane;
        const bool active = (ql < qe);
        const int  qid    = (int)g_qid[b][active ? ql : qs];
        const int  r      = b * N_UP + qid;

        const float qx = __ldg(&p_up[(size_t)r * 3 + 0]);
        const float qy = __ldg(&p_up[(size_t)r * 3 + 1]);
        const float qz = __ldg(&p_up[(size_t)r * 3 + 2]);
        const float qq = __fadd_rn(__fadd_rn(__fmul_rn(qx, qx), __fmul_rn(qy, qy)),
                                   __fmul_rn(qz, qz));

        uint64_t a0 = ~0ull, a1 = ~0ull, a2 = ~0ull, a3 = ~0ull;
        uint64_t c0 = ~0ull, c1 = ~0ull, c2 = ~0ull, c3 = ~0ull;

        #define INSERT4(K0, K1, K2, K3, key_)                                       \
        {                                                                           \
            const bool p0_ = key_ < K0, p1_ = key_ < K1;                            \
            const bool p2_ = key_ < K2, p3_ = key_ < K3;                            \
            K3 = p3_ ? (p2_ ? K2 : key_) : K3;                                      \
            K2 = p2_ ? (p1_ ? K1 : key_) : K2;                                      \
            K1 = p1_ ? (p0_ ? K0 : key_) : K1;                                      \
            K0 = p0_ ? key_ : K0;                                                   \
        }

        #define KEY_FROM(p_, oid_, key_)                                            \
            uint64_t key_;                                                          \
            {                                                                       \
                float dot_ = __fmul_rn(qx, p_.x);                                   \
                dot_ = fmaf(qy, p_.y, dot_);                                        \
                dot_ = fmaf(qz, p_.z, dot_);                                        \
                const float d2_ = __fadd_rn(__fadd_rn(qq, p_.w),                    \
                                            -__fmul_rn(2.0f, dot_));                \
                key_ = ((uint64_t)flip_f32(d2_) << 16) | (uint32_t)(oid_);          \
            }

        #define MAKE_KEY_G(j_, key_)                                                \
            const float4 p##key_ = __ldg(&pts[j_]);                                 \
            const uint32_t o##key_ = __ldg(&pid[j_]);                               \
            KEY_FROM(p##key_, o##key_, key_)

        #define SCAN_CELL_G(c)                                                      \
        {                                                                           \
            const int e_ = __ldg(&cst[(c) + 1]);                                    \
            int j_ = __ldg(&cst[(c)]);                                              \
            for (; j_ + 1 < e_; j_ += 2) {                                          \
                MAKE_KEY_G(j_,     keyA_);                                          \
                MAKE_KEY_G(j_ + 1, keyB_);                                          \
                INSERT4(a0, a1, a2, a3, keyA_);                                     \
                INSERT4(c0, c1, c2, c3, keyB_);                                     \
            }                                                                       \
            if (j_ < e_) {                                                          \
                MAKE_KEY_G(j_, keyA_);                                              \
                INSERT4(a0, a1, a2, a3, keyA_);                                     \
            }                                                                       \
        }

        // ---- Chebyshev <= 1 cube ----
        if (staged) {
            int j = 0;
            for (; j + 1 < total; j += 2) {
                const float4 pA = spts[j];
                const float4 pB = spts[j + 1];
                const unsigned short oA = ssid[j];
                const unsigned short oB = ssid[j + 1];
                KEY_FROM(pA, oA, keyA);
                KEY_FROM(pB, oB, keyB);
                INSERT4(a0, a1, a2, a3, keyA);
                INSERT4(c0, c1, c2, c3, keyB);
            }
            if (j < total) {
                const float4 pA = spts[j];
                const unsigned short oA = ssid[j];
                KEY_FROM(pA, oA, keyA);
                INSERT4(a0, a1, a2, a3, keyA);
            }
        } else {
            for (int z = z0c; z <= z1c; z++)
                for (int y = y0c; y <= y1c; y++)
                    for (int x = x0c; x <= x1c; x++)
                        SCAN_CELL_G(x | (y << 3) | (z << 6));
        }

        // ---- expanding shells (rare): merged bound + per-cell box pruning ----
        for (int rad = 2; rad < G; rad++) {
            uint64_t t0 = a0, t1 = a1, t2 = a2, t3 = a3;
            INSERT4(t0, t1, t2, t3, c0);
            INSERT4(t0, t1, t2, t3, c1);
            INSERT4(t0, t1, t2, t3, c2);
            INSERT4(t0, t1, t2, t3, c3);
            const float bd3v = unflip_f32((uint32_t)(t3 >> 16));

            const float dmin = (float)(rad - 1) * GH;
            const bool  done = !active || (bd3v <= dmin * dmin);
            if (__all_sync(0xffffffffu, done)) break;

            const float thresh = bd3v + PRUNE_MARGIN;

            const int z0 = max(0, cz - rad), z1 = min(G - 1, cz + rad);
            const int y0 = max(0, cy - rad), y1 = min(G - 1, cy + rad);
            const int x0 = max(0, cx - rad), x1 = min(G - 1, cx + rad);
            for (int z = z0; z <= z1; z++) {
                const int az = abs(z - cz);
                const float bz0 = z * GH, bz1 = bz0 + GH;
                const float ddz = fmaxf(0.0f, fmaxf(bz0 - qz, qz - bz1));
                for (int y = y0; y <= y1; y++) {
                    const int ay = abs(y - cy);
                    const float by0 = y * GH, by1 = by0 + GH;
                    const float ddy = fmaxf(0.0f, fmaxf(by0 - qy, qy - by1));
                    for (int x = x0; x <= x1; x++) {
                        const int ax = abs(x - cx);
                        if (max(ax, max(ay, az)) != rad) continue;
                        const float bx0 = x * GH, bx1 = bx0 + GH;
                        const float ddx = fmaxf(0.0f, fmaxf(bx0 - qx, qx - bx1));
                        const float cd2 = ddx * ddx + ddy * ddy + ddz * ddz;
                        const bool need = !done && (cd2 < thresh);
                        if (__any_sync(0xffffffffu, need))
                            SCAN_CELL_G(x | (y << 3) | (z << 6));
                    }
                }
            }
        }
        #undef SCAN_CELL_G
        #undef MAKE_KEY_G
        #undef KEY_FROM

        INSERT4(a0, a1, a2, a3, c0);
        INSERT4(a0, a1, a2, a3, c1);
        INSERT4(a0, a1, a2, a3, c2);
        INSERT4(a0, a1, a2, a3, c3);
        #undef INSERT4

        if (active) {
            const float d0  = unflip_f32((uint32_t)(a0 >> 16));
            const float d1  = unflip_f32((uint32_t)(a1 >> 16));
            const float d2v = unflip_f32((uint32_t)(a2 >> 16));
            const float d3  = unflip_f32((uint32_t)(a3 >> 16));
            const float w0 = 1.0f / fmaxf(d0, 1e-16f);
            const float w1 = 1.0f / fmaxf(d1, 1e-16f);
            const float w2 = 1.0f / fmaxf(d2v, 1e-16f);
            const float w3 = 1.0f / fmaxf(d3, 1e-16f);
            const float inv = 1.0f / (((w0 + w1) + w2) + w3);
            g_knn_idx[r * 4 + 0] = (int)(a0 & 0xFFFFu);
            g_knn_idx[r * 4 + 1] = (int)(a1 & 0xFFFFu);
            g_knn_idx[r * 4 + 2] = (int)(a2 & 0xFFFFu);
            g_knn_idx[r * 4 + 3] = (int)(a3 & 0xFFFFu);
            g_knn_w[r * 4 + 0] = w0 * inv;
            g_knn_w[r * 4 + 1] = w1 * inv;
            g_knn_w[r * 4 + 2] = w2 * inv;
            g_knn_w[r * 4 + 3] = w3 * inv;
        }
    }
}

// ---------------------------------------------------------------------------
// Tensor-core GEMM (mma.sync bf16, hi/lo split) + BN + ReLU (+ gather/add).
// CTA: 128x128, 8 warps (warp tile 32m x 64n), BK=32. (REVERTED to the
// known-good R11 version — the R12 B-resident restructure regressed.)
// ---------------------------------------------------------------------------
#define ROWB 80   // smem row pitch in bytes (32 bf16 = 64 B data + 16 B pad)

template <int KDIM, bool FUSED>
__global__ void __launch_bounds__(256) gemm_mma(
    const float* __restrict__ A,
    const __nv_bfloat16* __restrict__ Whi,
    const __nv_bfloat16* __restrict__ Wlo,
    const float* __restrict__ bias,
    const float* __restrict__ gamma,
    const float* __restrict__ beta,
    const float* __restrict__ mean,
    const float* __restrict__ var,
    float* __restrict__ outp)
{
    __shared__ __align__(16) uint8_t sAh[128 * ROWB];
    __shared__ __align__(16) uint8_t sAl[128 * ROWB];
    __shared__ __align__(16) uint8_t sBh[128 * ROWB];
    __shared__ __align__(16) uint8_t sBl[128 * ROWB];
    __shared__ float scale_s[C_OUT];
    __shared__ float shift_s[C_OUT];

    const int tid  = threadIdx.x;
    const int wid  = tid >> 5;
    const int lane = tid & 31;
    const int wm   = wid & 3;
    const int wn   = wid >> 2;
    const int row0 = blockIdx.x * 128;

    if (tid < C_OUT) {
        const float s = gamma[tid] * rsqrtf(var[tid] + 1e-5f);
        scale_s[tid] = s;
        shift_s[tid] = beta[tid] + (bias[tid] - mean[tid]) * s;
    }

    float acc[2][8][4];
    #pragma unroll
    for (int mt = 0; mt < 2; mt++)
        #pragma unroll
        for (int nt = 0; nt < 8; nt++)
            #pragma unroll
            for (int c = 0; c < 4; c++) acc[mt][nt][c] = 0.0f;

    const uint32_t sAh_b = smem_u32(sAh), sAl_b = smem_u32(sAl);
    const uint32_t sBh_b = smem_u32(sBh), sBl_b = smem_u32(sBl);
    const int a_row  = wm * 32 + (lane & 7) + ((lane >> 3) & 1) * 8;
    const int a_kby  = ((lane >> 4) & 1) * 16;
    const int b_nrow = wn * 64 + (lane & 7) + ((lane >> 4) & 1) * 8;
    const int b_kby  = ((lane >> 3) & 1) * 16;

    const int rr   = tid >> 1;
    const int half = tid & 1;

    for (int kc = 0; kc < KDIM / 32; kc++) {
        const int kt = kc * 32;

        {
            const float* ap = A + (size_t)(row0 + rr) * KDIM + kt + half * 16;
            const uint32_t wb = rr * ROWB + half * 32;
            #pragma unroll
            for (int q = 0; q < 2; q++) {
                const float4 v0 = *(const float4*)(ap + q * 8);
                const float4 v1 = *(const float4*)(ap + q * 8 + 4);
                __nv_bfloat162 h0 = __floats2bfloat162_rn(v0.x, v0.y);
                __nv_bfloat162 h1 = __floats2bfloat162_rn(v0.z, v0.w);
                __nv_bfloat162 h2 = __floats2bfloat162_rn(v1.x, v1.y);
                __nv_bfloat162 h3 = __floats2bfloat162_rn(v1.z, v1.w);
                __nv_bfloat162 l0 = __floats2bfloat162_rn(v0.x - __bfloat162float(h0.x),
                                                          v0.y - __bfloat162float(h0.y));
                __nv_bfloat162 l1 = __floats2bfloat162_rn(v0.z - __bfloat162float(h1.x),
                                                          v0.w - __bfloat162float(h1.y));
                __nv_bfloat162 l2 = __floats2bfloat162_rn(v1.x - __bfloat162float(h2.x),
                                                          v1.y - __bfloat162float(h2.y));
                __nv_bfloat162 l3 = __floats2bfloat162_rn(v1.z - __bfloat162float(h3.x),
                                                          v1.w - __bfloat162float(h3.y));
                *(uint4*)(sAh + wb + q * 16) = make_uint4(
                    *(uint32_t*)&h0, *(uint32_t*)&h1, *(uint32_t*)&h2, *(uint32_t*)&h3);
                *(uint4*)(sAl + wb + q * 16) = make_uint4(
                    *(uint32_t*)&l0, *(uint32_t*)&l1, *(uint32_t*)&l2, *(uint32_t*)&l3);
            }
        }
        {
            const __nv_bfloat16* wh = Whi + (size_t)rr * KDIM + kt + half * 16;
            const __nv_bfloat16* wl = Wlo + (size_t)rr * KDIM + kt + half * 16;
            const uint32_t wb = rr * ROWB + half * 32;
            *(uint4*)(sBh + wb)      = *(const uint4*)(wh);
            *(uint4*)(sBh + wb + 16) = *(const uint4*)(wh + 8);
            *(uint4*)(sBl + wb)      = *(const uint4*)(wl);
            *(uint4*)(sBl + wb + 16) = *(const uint4*)(wl + 8);
        }
        __syncthreads();

        #pragma unroll
        for (int kk = 0; kk < 32; kk += 16) {
            uint32_t ah[2][4], al[2][4];
            #pragma unroll
            for (int mt = 0; mt < 2; mt++) {
                const uint32_t ao = (uint32_t)((a_row + mt * 16) * ROWB + kk * 2 + a_kby);
                LDSM_X4(ah[mt][0], ah[mt][1], ah[mt][2], ah[mt][3], sAh_b + ao);
                LDSM_X4(al[mt][0], al[mt][1], al[mt][2], al[mt][3], sAl_b + ao);
            }
            #pragma unroll
            for (int ntp = 0; ntp < 4; ntp++) {
                const uint32_t bo = (uint32_t)((b_nrow + ntp * 16) * ROWB + kk * 2 + b_kby);
                uint32_t bh0, bh1, bh2, bh3, bl0, bl1, bl2, bl3;
                LDSM_X4(bh0, bh1, bh2, bh3, sBh_b + bo);
                LDSM_X4(bl0, bl1, bl2, bl3, sBl_b + bo);
                #pragma unroll
                for (int mt = 0; mt < 2; mt++) {
                    mma_bf16(acc[mt][ntp * 2 + 0], ah[mt], bh0, bh1);
                    mma_bf16(acc[mt][ntp * 2 + 0], al[mt], bh0, bh1);
                    mma_bf16(acc[mt][ntp * 2 + 1], ah[mt], bh2, bh3);
                    mma_bf16(acc[mt][ntp * 2 + 1], al[mt], bh2, bh3);
                    mma_bf16(acc[mt][ntp * 2 + 0], ah[mt], bl0, bl1);
                    mma_bf16(acc[mt][ntp * 2 + 1], ah[mt], bl2, bl3);
                }
            }
        }
        __syncthreads();
    }

    float* dst = FUSED ? outp : g_xd;
    const int quad = lane >> 2;
    const int tq2  = (lane & 3) * 2;

    #pragma unroll
    for (int mt = 0; mt < 2; mt++) {
        #pragma unroll
        for (int h = 0; h < 2; h++) {
            const int r = row0 + wm * 32 + mt * 16 + quad + h * 8;

            const float* fr[KNN];
            float wk[KNN];
            if (FUSED) {
                const int bidx = r >> 14;
                const float* xdb = g_xd + (size_t)bidx * N_DOWN * C_OUT;
                #pragma unroll
                for (int k = 0; k < KNN; k++) {
                    fr[k] = xdb + (size_t)g_knn_idx[r * 4 + k] * C_OUT;
                    wk[k] = g_knn_w[r * 4 + k];
                }
            }

            #pragma unroll
            for (int nt = 0; nt < 8; nt++) {
                const int col = wn * 64 + nt * 8 + tq2;
                float o0 = fmaxf(fmaf(acc[mt][nt][h * 2 + 0], scale_s[col],     shift_s[col]),     0.0f);
                float o1 = fmaxf(fmaf(acc[mt][nt][h * 2 + 1], scale_s[col + 1], shift_s[col + 1]), 0.0f);
                if (FUSED) {
                    #pragma unroll
                    for (int k = 0; k < KNN; k++) {
                        const float2 v = *(const float2*)(fr[k] + col);
                        o0 = fmaf(wk[k], v.x, o0);
                        o1 = fmaf(wk[k], v.y, o1);
                    }
                }
                *(float2*)(dst + (size_t)r * C_OUT + col) = make_float2(o0, o1);
            }
        }
    }
}

// ---------------------------------------------------------------------------
// Launch: fork-join stream overlap (kNN || down-GEMM), graph-capturable.
// ---------------------------------------------------------------------------
extern "C" void kernel_launch(void* const* d_in, const int* in_sizes, int n_in,
                              void* d_out, int out_size)
{
    const float* x_down  = (const float*)d_in[0];
    const float* x_up    = (const float*)d_in[1];
    const float* p_down  = (const float*)d_in[2];
    const float* p_up    = (const float*)d_in[3];
    const float* W_down  = (const float*)d_in[4];
    const float* b_down  = (const float*)d_in[5];
    const float* g_down  = (const float*)d_in[6];
    const float* be_down = (const float*)d_in[7];
    const float* m_down  = (const float*)d_in[8];
    const float* v_down  = (const float*)d_in[9];
    const float* W_up    = (const float*)d_in[10];
    const float* b_up    = (const float*)d_in[11];
    const float* g_up    = (const float*)d_in[12];
    const float* be_up   = (const float*)d_in[13];
    const float* m_up    = (const float*)d_in[14];
    const float* v_up    = (const float*)d_in[15];
    float* out = (float*)d_out;

    __nv_bfloat16 *wdh, *wdl, *wuh, *wul;
    cudaGetSymbolAddress((void**)&wdh, g_Wd_hi);
    cudaGetSymbolAddress((void**)&wdl, g_Wd_lo);
    cudaGetSymbolAddress((void**)&wuh, g_Wu_hi);
    cudaGetSymbolAddress((void**)&wul, g_Wu_lo);

    static cudaStream_t s_knn = nullptr;
    static cudaEvent_t  ev_setup = nullptr, ev_knn = nullptr;
    if (s_knn == nullptr) {
        cudaStreamCreateWithFlags(&s_knn, cudaStreamNonBlocking);
        cudaEventCreateWithFlags(&ev_setup, cudaEventDisableTiming);
        cudaEventCreateWithFlags(&ev_knn,   cudaEventDisableTiming);
    }

    // 1) fused setup on the main (capture) stream
    setup_kernel<<<12, 512>>>(p_down, p_up, W_down, W_up);
    cudaEventRecord(ev_setup, 0);

    // 2) kNN on side stream, concurrent with down-GEMM on main stream
    cudaStreamWaitEvent(s_knn, ev_setup, 0);
    dim3 qgrid(NCELL, B_SZ);
    knn_query<<<qgrid, 128, 0, s_knn>>>(p_up);
    cudaEventRecord(ev_knn, s_knn);

    // 3) down MLP -> g_xd (main stream, overlaps kNN)
    gemm_mma<C_IN, false><<<M_DOWN / 128, 256>>>(
        x_down, wdh, wdl, b_down, g_down, be_down, m_down, v_down, nullptr);

    // 4) join, then up MLP + gather + add -> out
    cudaStreamWaitEvent(0, ev_knn, 0);
    gemm_mma<C_OUT, true><<<M_UP / 128, 256>>>(
        x_up, wuh, wul, b_up, g_up, be_up, m_up, v_up, out);
}

// round 14
// speedup vs baseline: 1.1806x; 1.0904x over previous
#include <cuda_runtime.h>
#include <cuda_bf16.h>
#include <cstdint>

// ---------------------------------------------------------------------------
// Problem shape (fixed)
// ---------------------------------------------------------------------------
#define B_SZ   4
#define N_DOWN 4096
#define N_UP   16384
#define C_IN   256
#define C_OUT  128
#define KNN    4

#define M_DOWN (B_SZ * N_DOWN)   // 16384
#define M_UP   (B_SZ * N_UP)     // 65536

// Spatial grid: 8x8x8 over [0,1]^3
#define G      8
#define NCELL  (G * G * G)
#define GH     0.125f

// ---------------------------------------------------------------------------
// Helpers
// ---------------------------------------------------------------------------
__device__ __forceinline__ uint32_t smem_u32(const void* p) {
    uint32_t a;
    asm("{ .reg .u64 t; cvta.to.shared.u64 t, %1; cvt.u32.u64 %0, t; }" : "=r"(a) : "l"(p));
    return a;
}

#define LDSM_X4(r0, r1, r2, r3, addr)                                             \
    asm volatile("ldmatrix.sync.aligned.m8n8.x4.shared.b16 {%0,%1,%2,%3}, [%4];"  \
                 : "=r"(r0), "=r"(r1), "=r"(r2), "=r"(r3) : "r"(addr))

__device__ __forceinline__ void mma_bf16(float* c, const uint32_t* a,
                                         uint32_t b0, uint32_t b1) {
    asm volatile(
        "mma.sync.aligned.m16n8k16.row.col.f32.bf16.bf16.f32 "
        "{%0,%1,%2,%3}, {%4,%5,%6,%7}, {%8,%9}, {%0,%1,%2,%3};"
        : "+f"(c[0]), "+f"(c[1]), "+f"(c[2]), "+f"(c[3])
        : "r"(a[0]), "r"(a[1]), "r"(a[2]), "r"(a[3]), "r"(b0), "r"(b1));
}

// monotone key: flip fp32 bits so unsigned compare == float compare
__device__ __forceinline__ uint32_t flip_f32(float f) {
    const uint32_t fb = __float_as_uint(f);
    return (fb & 0x80000000u) ? ~fb : (fb | 0x80000000u);
}
__device__ __forceinline__ float unflip_f32(uint32_t u) {
    return __uint_as_float((u & 0x80000000u) ? (u ^ 0x80000000u) : ~u);
}

__device__ __forceinline__ int cell_of(float px, float py, float pz) {
    const int cx = min(G - 1, (int)(px * (float)G));
    const int cy = min(G - 1, (int)(py * (float)G));
    const int cz = min(G - 1, (int)(pz * (float)G));
    return cx | (cy << 3) | (cz << 6);
}

// ---------------------------------------------------------------------------
// Device-global scratch
// ---------------------------------------------------------------------------
__device__ float g_xd[M_DOWN * C_OUT];              // 8 MB
__device__ int   g_knn_idx[M_UP * KNN];
__device__ float g_knn_w[M_UP * KNN];
__device__ float4         g_pts[B_SZ][N_DOWN];
__device__ uint32_t       g_pid32[B_SZ][N_DOWN];
__device__ int            g_cellstart[B_SZ][NCELL + 1];
__device__ unsigned short g_qid[B_SZ][N_UP];
__device__ int            g_qcellstart[B_SZ][NCELL + 1];
__device__ __nv_bfloat16 g_Wd_hi[C_OUT * C_IN];
__device__ __nv_bfloat16 g_Wd_lo[C_OUT * C_IN];
__device__ __nv_bfloat16 g_Wu_hi[C_OUT * C_OUT];
__device__ __nv_bfloat16 g_Wu_lo[C_OUT * C_OUT];

// ---------------------------------------------------------------------------
// Fused setup: ONE launch, 12 independent blocks @512 threads.
// ---------------------------------------------------------------------------
template <int NPTS, bool WRITE_PTS>
__device__ void build_one_batch(const float* __restrict__ pb, int b)
{
    __shared__ int counts[NCELL];
    __shared__ int s1[NCELL];
    __shared__ int s2[NCELL];

    const int t = threadIdx.x;
    counts[t] = 0;
    __syncthreads();

    for (int j = t; j < NPTS; j += 512)
        atomicAdd(&counts[cell_of(pb[j * 3], pb[j * 3 + 1], pb[j * 3 + 2])], 1);
    __syncthreads();

    s1[t] = counts[t];
    __syncthreads();
    int* src = s1;
    int* dst = s2;
    for (int d = 1; d < NCELL; d <<= 1) {
        int v = src[t];
        if (t >= d) v += src[t - d];
        dst[t] = v;
        __syncthreads();
        int* tmp = src; src = dst; dst = tmp;
    }
    const int excl = src[t] - counts[t];
    if (WRITE_PTS) {
        g_cellstart[b][t] = excl;
        if (t == 0) g_cellstart[b][NCELL] = NPTS;
    } else {
        g_qcellstart[b][t] = excl;
        if (t == 0) g_qcellstart[b][NCELL] = NPTS;
    }
    counts[t] = excl;
    __syncthreads();

    for (int j = t; j < NPTS; j += 512) {
        const float px = pb[j * 3], py = pb[j * 3 + 1], pz = pb[j * 3 + 2];
        const int slot = atomicAdd(&counts[cell_of(px, py, pz)], 1);
        if (WRITE_PTS) {
            const float pp = __fadd_rn(__fadd_rn(__fmul_rn(px, px), __fmul_rn(py, py)),
                                       __fmul_rn(pz, pz));
            g_pts[b][slot]   = make_float4(px, py, pz, pp);
            g_pid32[b][slot] = (uint32_t)j;
        } else {
            g_qid[b][slot] = (unsigned short)j;
        }
    }
}

__global__ void __launch_bounds__(512) setup_kernel(
    const float* __restrict__ p_down,
    const float* __restrict__ p_up,
    const float* __restrict__ W_down,
    const float* __restrict__ W_up)
{
    const int bb = blockIdx.x;
    if (bb < 4) {
        build_one_batch<N_DOWN, true>(p_down + (size_t)bb * N_DOWN * 3, bb);
    } else if (bb < 8) {
        build_one_batch<N_UP, false>(p_up + (size_t)(bb - 4) * N_UP * 3, bb - 4);
    } else {
        for (int idx = (bb - 8) * 512 + threadIdx.x;
             idx < C_OUT * C_IN + C_OUT * C_OUT; idx += 4 * 512) {
            if (idx < C_OUT * C_IN) {
                const int n = idx >> 8;
                const int k = idx & 255;
                const float v = W_down[k * C_OUT + n];
                const __nv_bfloat16 h = __float2bfloat16(v);
                g_Wd_hi[n * C_IN + k] = h;
                g_Wd_lo[n * C_IN + k] = __float2bfloat16(v - __bfloat162float(h));
            } else {
                const int j = idx - C_OUT * C_IN;
                const int n = j >> 7;
                const int k = j & 127;
                const float v = W_up[k * C_OUT + n];
                const __nv_bfloat16 h = __float2bfloat16(v);
                g_Wu_hi[n * C_OUT + k] = h;
                g_Wu_lo[n * C_OUT + k] = __float2bfloat16(v - __bfloat162float(h));
            }
        }
    }
}

// ---------------------------------------------------------------------------
// kNN (unchanged from R13, passing): block per cell, staged Chebyshev-1 cube
// in smem, dual-bank branchless top-4, exact merged bounds, pruned shells.
// u64 key = (flip(d2) << 16) | orig_id == stable jax top_k semantics.
// ---------------------------------------------------------------------------
#define PRUNE_MARGIN 1e-5f
#define STAGE_CAP    1024

__global__ void __launch_bounds__(128) knn_query(const float* __restrict__ p_up)
{
    __shared__ float4         spts[STAGE_CAP];
    __shared__ unsigned short ssid[STAGE_CAP];

    const int b    = blockIdx.y;
    const int cell = blockIdx.x;
    const int warp = threadIdx.x >> 5;
    const int lane = threadIdx.x & 31;
    const int tid  = threadIdx.x;
    const int cx = cell & 7, cy = (cell >> 3) & 7, cz = cell >> 6;

    const float4*   pts = g_pts[b];
    const uint32_t* pid = g_pid32[b];
    const int*      cst = g_cellstart[b];

    const int z0c = max(0, cz - 1), z1c = min(G - 1, cz + 1);
    const int y0c = max(0, cy - 1), y1c = min(G - 1, cy + 1);
    const int x0c = max(0, cx - 1), x1c = min(G - 1, cx + 1);

    int base = 0;
    for (int z = z0c; z <= z1c; z++)
        for (int y = y0c; y <= y1c; y++)
            for (int x = x0c; x <= x1c; x++) {
                const int c = x | (y << 3) | (z << 6);
                const int s = __ldg(&cst[c]);
                const int e = __ldg(&cst[c + 1]);
                const int len = e - s;
                if (base + len <= STAGE_CAP) {
                    for (int i = tid; i < len; i += 128) {
                        spts[base + i] = __ldg(&pts[s + i]);
                        ssid[base + i] = (unsigned short)__ldg(&pid[s + i]);
                    }
                }
                base += len;
            }
    const bool staged = (base <= STAGE_CAP);
    const int  total  = base;
    __syncthreads();

    const int qs = g_qcellstart[b][cell];
    const int qe = g_qcellstart[b][cell + 1];

    for (int q0 = qs + warp * 32; q0 < qe; q0 += 128) {
        const int  ql     = q0 + lane;
        const bool active = (ql < qe);
        const int  qid    = (int)g_qid[b][active ? ql : qs];
        const int  r      = b * N_UP + qid;

        const float qx = __ldg(&p_up[(size_t)r * 3 + 0]);
        const float qy = __ldg(&p_up[(size_t)r * 3 + 1]);
        const float qz = __ldg(&p_up[(size_t)r * 3 + 2]);
        const float qq = __fadd_rn(__fadd_rn(__fmul_rn(qx, qx), __fmul_rn(qy, qy)),
                                   __fmul_rn(qz, qz));

        uint64_t a0 = ~0ull, a1 = ~0ull, a2 = ~0ull, a3 = ~0ull;
        uint64_t c0 = ~0ull, c1 = ~0ull, c2 = ~0ull, c3 = ~0ull;

        #define INSERT4(K0, K1, K2, K3, key_)                                       \
        {                                                                           \
            const bool p0_ = key_ < K0, p1_ = key_ < K1;                            \
            const bool p2_ = key_ < K2, p3_ = key_ < K3;                            \
            K3 = p3_ ? (p2_ ? K2 : key_) : K3;                                      \
            K2 = p2_ ? (p1_ ? K1 : key_) : K2;                                      \
            K1 = p1_ ? (p0_ ? K0 : key_) : K1;                                      \
            K0 = p0_ ? key_ : K0;                                                   \
        }

        #define KEY_FROM(p_, oid_, key_)                                            \
            uint64_t key_;                                                          \
            {                                                                       \
                float dot_ = __fmul_rn(qx, p_.x);                                   \
                dot_ = fmaf(qy, p_.y, dot_);                                        \
                dot_ = fmaf(qz, p_.z, dot_);                                        \
                const float d2_ = __fadd_rn(__fadd_rn(qq, p_.w),                    \
                                            -__fmul_rn(2.0f, dot_));                \
                key_ = ((uint64_t)flip_f32(d2_) << 16) | (uint32_t)(oid_);          \
            }

        #define MAKE_KEY_G(j_, key_)                                                \
            const float4 p##key_ = __ldg(&pts[j_]);                                 \
            const uint32_t o##key_ = __ldg(&pid[j_]);                               \
            KEY_FROM(p##key_, o##key_, key_)

        #define SCAN_CELL_G(c)                                                      \
        {                                                                           \
            const int e_ = __ldg(&cst[(c) + 1]);                                    \
            int j_ = __ldg(&cst[(c)]);                                              \
            for (; j_ + 1 < e_; j_ += 2) {                                          \
                MAKE_KEY_G(j_,     keyA_);                                          \
                MAKE_KEY_G(j_ + 1, keyB_);                                          \
                INSERT4(a0, a1, a2, a3, keyA_);                                     \
                INSERT4(c0, c1, c2, c3, keyB_);                                     \
            }                                                                       \
            if (j_ < e_) {                                                          \
                MAKE_KEY_G(j_, keyA_);                                              \
                INSERT4(a0, a1, a2, a3, keyA_);                                     \
            }                                                                       \
        }

        if (staged) {
            int j = 0;
            for (; j + 1 < total; j += 2) {
                const float4 pA = spts[j];
                const float4 pB = spts[j + 1];
                const unsigned short oA = ssid[j];
                const unsigned short oB = ssid[j + 1];
                KEY_FROM(pA, oA, keyA);
                KEY_FROM(pB, oB, keyB);
                INSERT4(a0, a1, a2, a3, keyA);
                INSERT4(c0, c1, c2, c3, keyB);
            }
            if (j < total) {
                const float4 pA = spts[j];
                const unsigned short oA = ssid[j];
                KEY_FROM(pA, oA, keyA);
                INSERT4(a0, a1, a2, a3, keyA);
            }
        } else {
            for (int z = z0c; z <= z1c; z++)
                for (int y = y0c; y <= y1c; y++)
                    for (int x = x0c; x <= x1c; x++)
                        SCAN_CELL_G(x | (y << 3) | (z << 6));
        }

        for (int rad = 2; rad < G; rad++) {
            uint64_t t0 = a0, t1 = a1, t2 = a2, t3 = a3;
            INSERT4(t0, t1, t2, t3, c0);
            INSERT4(t0, t1, t2, t3, c1);
            INSERT4(t0, t1, t2, t3, c2);
            INSERT4(t0, t1, t2, t3, c3);
            const float bd3v = unflip_f32((uint32_t)(t3 >> 16));

            const float dmin = (float)(rad - 1) * GH;
            const bool  done = !active || (bd3v <= dmin * dmin);
            if (__all_sync(0xffffffffu, done)) break;

            const float thresh = bd3v + PRUNE_MARGIN;

            const int z0 = max(0, cz - rad), z1 = min(G - 1, cz + rad);
            const int y0 = max(0, cy - rad), y1 = min(G - 1, cy + rad);
            const int x0 = max(0, cx - rad), x1 = min(G - 1, cx + rad);
            for (int z = z0; z <= z1; z++) {
                const int az = abs(z - cz);
                const float bz0 = z * GH, bz1 = bz0 + GH;
                const float ddz = fmaxf(0.0f, fmaxf(bz0 - qz, qz - bz1));
                for (int y = y0; y <= y1; y++) {
                    const int ay = abs(y - cy);
                    const float by0 = y * GH, by1 = by0 + GH;
                    const float ddy = fmaxf(0.0f, fmaxf(by0 - qy, qy - by1));
                    for (int x = x0; x <= x1; x++) {
                        const int ax = abs(x - cx);
                        if (max(ax, max(ay, az)) != rad) continue;
                        const float bx0 = x * GH, bx1 = bx0 + GH;
                        const float ddx = fmaxf(0.0f, fmaxf(bx0 - qx, qx - bx1));
                        const float cd2 = ddx * ddx + ddy * ddy + ddz * ddz;
                        const bool need = !done && (cd2 < thresh);
                        if (__any_sync(0xffffffffu, need))
                            SCAN_CELL_G(x | (y << 3) | (z << 6));
                    }
                }
            }
        }
        #undef SCAN_CELL_G
        #undef MAKE_KEY_G
        #undef KEY_FROM

        INSERT4(a0, a1, a2, a3, c0);
        INSERT4(a0, a1, a2, a3, c1);
        INSERT4(a0, a1, a2, a3, c2);
        INSERT4(a0, a1, a2, a3, c3);
        #undef INSERT4

        if (active) {
            const float d0  = unflip_f32((uint32_t)(a0 >> 16));
            const float d1  = unflip_f32((uint32_t)(a1 >> 16));
            const float d2v = unflip_f32((uint32_t)(a2 >> 16));
            const float d3  = unflip_f32((uint32_t)(a3 >> 16));
            const float w0 = 1.0f / fmaxf(d0, 1e-16f);
            const float w1 = 1.0f / fmaxf(d1, 1e-16f);
            const float w2 = 1.0f / fmaxf(d2v, 1e-16f);
            const float w3 = 1.0f / fmaxf(d3, 1e-16f);
            const float inv = 1.0f / (((w0 + w1) + w2) + w3);
            g_knn_idx[r * 4 + 0] = (int)(a0 & 0xFFFFu);
            g_knn_idx[r * 4 + 1] = (int)(a1 & 0xFFFFu);
            g_knn_idx[r * 4 + 2] = (int)(a2 & 0xFFFFu);
            g_knn_idx[r * 4 + 3] = (int)(a3 & 0xFFFFu);
            g_knn_w[r * 4 + 0] = w0 * inv;
            g_knn_w[r * 4 + 1] = w1 * inv;
            g_knn_w[r * 4 + 2] = w2 * inv;
            g_knn_w[r * 4 + 3] = w3 * inv;
        }
    }
}

// ---------------------------------------------------------------------------
// Tensor-core GEMM (mma.sync bf16, hi/lo split) + BN + ReLU -> dst.
// No gather in the epilogue anymore: the up-GEMM main part has NO dependency
// on kNN/down, enabling 3-way stream overlap. Arithmetic identical to the
// passing fused version up to the gather (which moves to gather_add).
// ---------------------------------------------------------------------------
#define ROWB 80   // smem row pitch in bytes (32 bf16 = 64 B data + 16 B pad)

template <int KDIM>
__global__ void __launch_bounds__(256) gemm_mma(
    const float* __restrict__ A,
    const __nv_bfloat16* __restrict__ Whi,
    const __nv_bfloat16* __restrict__ Wlo,
    const float* __restrict__ bias,
    const float* __restrict__ gamma,
    const float* __restrict__ beta,
    const float* __restrict__ mean,
    const float* __restrict__ var,
    float* __restrict__ dst)
{
    __shared__ __align__(16) uint8_t sAh[128 * ROWB];
    __shared__ __align__(16) uint8_t sAl[128 * ROWB];
    __shared__ __align__(16) uint8_t sBh[128 * ROWB];
    __shared__ __align__(16) uint8_t sBl[128 * ROWB];
    __shared__ float scale_s[C_OUT];
    __shared__ float shift_s[C_OUT];

    const int tid  = threadIdx.x;
    const int wid  = tid >> 5;
    const int lane = tid & 31;
    const int wm   = wid & 3;
    const int wn   = wid >> 2;
    const int row0 = blockIdx.x * 128;

    if (tid < C_OUT) {
        const float s = gamma[tid] * rsqrtf(var[tid] + 1e-5f);
        scale_s[tid] = s;
        shift_s[tid] = beta[tid] + (bias[tid] - mean[tid]) * s;
    }

    float acc[2][8][4];
    #pragma unroll
    for (int mt = 0; mt < 2; mt++)
        #pragma unroll
        for (int nt = 0; nt < 8; nt++)
            #pragma unroll
            for (int c = 0; c < 4; c++) acc[mt][nt][c] = 0.0f;

    const uint32_t sAh_b = smem_u32(sAh), sAl_b = smem_u32(sAl);
    const uint32_t sBh_b = smem_u32(sBh), sBl_b = smem_u32(sBl);
    const int a_row  = wm * 32 + (lane & 7) + ((lane >> 3) & 1) * 8;
    const int a_kby  = ((lane >> 4) & 1) * 16;
    const int b_nrow = wn * 64 + (lane & 7) + ((lane >> 4) & 1) * 8;
    const int b_kby  = ((lane >> 3) & 1) * 16;

    const int rr   = tid >> 1;
    const int half = tid & 1;

    for (int kc = 0; kc < KDIM / 32; kc++) {
        const int kt = kc * 32;

        {
            const float* ap = A + (size_t)(row0 + rr) * KDIM + kt + half * 16;
            const uint32_t wb = rr * ROWB + half * 32;
            #pragma unroll
            for (int q = 0; q < 2; q++) {
                const float4 v0 = *(const float4*)(ap + q * 8);
                const float4 v1 = *(const float4*)(ap + q * 8 + 4);
                __nv_bfloat162 h0 = __floats2bfloat162_rn(v0.x, v0.y);
                __nv_bfloat162 h1 = __floats2bfloat162_rn(v0.z, v0.w);
                __nv_bfloat162 h2 = __floats2bfloat162_rn(v1.x, v1.y);
                __nv_bfloat162 h3 = __floats2bfloat162_rn(v1.z, v1.w);
                __nv_bfloat162 l0 = __floats2bfloat162_rn(v0.x - __bfloat162float(h0.x),
                                                          v0.y - __bfloat162float(h0.y));
                __nv_bfloat162 l1 = __floats2bfloat162_rn(v0.z - __bfloat162float(h1.x),
                                                          v0.w - __bfloat162float(h1.y));
                __nv_bfloat162 l2 = __floats2bfloat162_rn(v1.x - __bfloat162float(h2.x),
                                                          v1.y - __bfloat162float(h2.y));
                __nv_bfloat162 l3 = __floats2bfloat162_rn(v1.z - __bfloat162float(h3.x),
                                                          v1.w - __bfloat162float(h3.y));
                *(uint4*)(sAh + wb + q * 16) = make_uint4(
                    *(uint32_t*)&h0, *(uint32_t*)&h1, *(uint32_t*)&h2, *(uint32_t*)&h3);
                *(uint4*)(sAl + wb + q * 16) = make_uint4(
                    *(uint32_t*)&l0, *(uint32_t*)&l1, *(uint32_t*)&l2, *(uint32_t*)&l3);
            }
        }
        {
            const __nv_bfloat16* wh = Whi + (size_t)rr * KDIM + kt + half * 16;
            const __nv_bfloat16* wl = Wlo + (size_t)rr * KDIM + kt + half * 16;
            const uint32_t wb = rr * ROWB + half * 32;
            *(uint4*)(sBh + wb)      = *(const uint4*)(wh);
            *(uint4*)(sBh + wb + 16) = *(const uint4*)(wh + 8);
            *(uint4*)(sBl + wb)      = *(const uint4*)(wl);
            *(uint4*)(sBl + wb + 16) = *(const uint4*)(wl + 8);
        }
        __syncthreads();

        #pragma unroll
        for (int kk = 0; kk < 32; kk += 16) {
            uint32_t ah[2][4], al[2][4];
            #pragma unroll
            for (int mt = 0; mt < 2; mt++) {
                const uint32_t ao = (uint32_t)((a_row + mt * 16) * ROWB + kk * 2 + a_kby);
                LDSM_X4(ah[mt][0], ah[mt][1], ah[mt][2], ah[mt][3], sAh_b + ao);
                LDSM_X4(al[mt][0], al[mt][1], al[mt][2], al[mt][3], sAl_b + ao);
            }
            #pragma unroll
            for (int ntp = 0; ntp < 4; ntp++) {
                const uint32_t bo = (uint32_t)((b_nrow + ntp * 16) * ROWB + kk * 2 + b_kby);
                uint32_t bh0, bh1, bh2, bh3, bl0, bl1, bl2, bl3;
                LDSM_X4(bh0, bh1, bh2, bh3, sBh_b + bo);
                LDSM_X4(bl0, bl1, bl2, bl3, sBl_b + bo);
                #pragma unroll
                for (int mt = 0; mt < 2; mt++) {
                    mma_bf16(acc[mt][ntp * 2 + 0], ah[mt], bh0, bh1);
                    mma_bf16(acc[mt][ntp * 2 + 0], al[mt], bh0, bh1);
                    mma_bf16(acc[mt][ntp * 2 + 1], ah[mt], bh2, bh3);
                    mma_bf16(acc[mt][ntp * 2 + 1], al[mt], bh2, bh3);
                    mma_bf16(acc[mt][ntp * 2 + 0], ah[mt], bl0, bl1);
                    mma_bf16(acc[mt][ntp * 2 + 1], ah[mt], bl2, bl3);
                }
            }
        }
        __syncthreads();
    }

    const int quad = lane >> 2;
    const int tq2  = (lane & 3) * 2;
    #pragma unroll
    for (int mt = 0; mt < 2; mt++) {
        #pragma unroll
        for (int h = 0; h < 2; h++) {
            const int r = row0 + wm * 32 + mt * 16 + quad + h * 8;
            #pragma unroll
            for (int nt = 0; nt < 8; nt++) {
                const int col = wn * 64 + nt * 8 + tq2;
                float o0 = fmaxf(fmaf(acc[mt][nt][h * 2 + 0], scale_s[col],     shift_s[col]),     0.0f);
                float o1 = fmaxf(fmaf(acc[mt][nt][h * 2 + 1], scale_s[col + 1], shift_s[col + 1]), 0.0f);
                *(float2*)(dst + (size_t)r * C_OUT + col) = make_float2(o0, o1);
            }
        }
    }
}

// ---------------------------------------------------------------------------
// gather_add: out[r] += sum_k w_k * g_xd[idx_k]  (fp32, fma order k=0..3 —
// identical arithmetic to the previously-fused epilogue).
// 8 warps/block, 1 warp per output row, 1 float4 per lane.
// ---------------------------------------------------------------------------
__global__ void __launch_bounds__(256) gather_add(float* __restrict__ out)
{
    const int r    = blockIdx.x * 8 + (threadIdx.x >> 5);
    const int lane = threadIdx.x & 31;
    const int bidx = r >> 14;                       // r / N_UP
    const float* xdb = g_xd + (size_t)bidx * N_DOWN * C_OUT;

    const int4   id = *(const int4*)&g_knn_idx[r * 4];
    const float4 w  = *(const float4*)&g_knn_w[r * 4];

    float4 o = *(float4*)(out + (size_t)r * C_OUT + lane * 4);
    const float4 v0 = __ldg((const float4*)(xdb + (size_t)id.x * C_OUT + lane * 4));
    const float4 v1 = __ldg((const float4*)(xdb + (size_t)id.y * C_OUT + lane * 4));
    const float4 v2 = __ldg((const float4*)(xdb + (size_t)id.z * C_OUT + lane * 4));
    const float4 v3 = __ldg((const float4*)(xdb + (size_t)id.w * C_OUT + lane * 4));

    o.x = fmaf(w.x, v0.x, o.x); o.y = fmaf(w.x, v0.y, o.y);
    o.z = fmaf(w.x, v0.z, o.z); o.w = fmaf(w.x, v0.w, o.w);
    o.x = fmaf(w.y, v1.x, o.x); o.y = fmaf(w.y, v1.y, o.y);
    o.z = fmaf(w.y, v1.z, o.z); o.w = fmaf(w.y, v1.w, o.w);
    o.x = fmaf(w.z, v2.x, o.x); o.y = fmaf(w.z, v2.y, o.y);
    o.z = fmaf(w.z, v2.z, o.z); o.w = fmaf(w.z, v2.w, o.w);
    o.x = fmaf(w.w, v3.x, o.x); o.y = fmaf(w.w, v3.y, o.y);
    o.z = fmaf(w.w, v3.z, o.z); o.w = fmaf(w.w, v3.w, o.w);

    *(float4*)(out + (size_t)r * C_OUT + lane * 4) = o;
}

// ---------------------------------------------------------------------------
// Launch: setup -> { kNN || down-GEMM || up-main } -> gather_add.
// Three-stream fork-join, graph-capturable (streams/events made once).
// ---------------------------------------------------------------------------
extern "C" void kernel_launch(void* const* d_in, const int* in_sizes, int n_in,
                              void* d_out, int out_size)
{
    const float* x_down  = (const float*)d_in[0];
    const float* x_up    = (const float*)d_in[1];
    const float* p_down  = (const float*)d_in[2];
    const float* p_up    = (const float*)d_in[3];
    const float* W_down  = (const float*)d_in[4];
    const float* b_down  = (const float*)d_in[5];
    const float* g_down  = (const float*)d_in[6];
    const float* be_down = (const float*)d_in[7];
    const float* m_down  = (const float*)d_in[8];
    const float* v_down  = (const float*)d_in[9];
    const float* W_up    = (const float*)d_in[10];
    const float* b_up    = (const float*)d_in[11];
    const float* g_up    = (const float*)d_in[12];
    const float* be_up   = (const float*)d_in[13];
    const float* m_up    = (const float*)d_in[14];
    const float* v_up    = (const float*)d_in[15];
    float* out = (float*)d_out;

    __nv_bfloat16 *wdh, *wdl, *wuh, *wul;
    cudaGetSymbolAddress((void**)&wdh, g_Wd_hi);
    cudaGetSymbolAddress((void**)&wdl, g_Wd_lo);
    cudaGetSymbolAddress((void**)&wuh, g_Wu_hi);
    cudaGetSymbolAddress((void**)&wul, g_Wu_lo);
    float* xd;
    cudaGetSymbolAddress((void**)&xd, g_xd);

    static cudaStream_t s_knn = nullptr, s_down = nullptr;
    static cudaEvent_t  ev_setup = nullptr, ev_knn = nullptr, ev_down = nullptr;
    if (s_knn == nullptr) {
        cudaStreamCreateWithFlags(&s_knn,  cudaStreamNonBlocking);
        cudaStreamCreateWithFlags(&s_down, cudaStreamNonBlocking);
        cudaEventCreateWithFlags(&ev_setup, cudaEventDisableTiming);
        cudaEventCreateWithFlags(&ev_knn,   cudaEventDisableTiming);
        cudaEventCreateWithFlags(&ev_down,  cudaEventDisableTiming);
    }

    // 1) fused setup on the main stream
    setup_kernel<<<12, 512>>>(p_down, p_up, W_down, W_up);
    cudaEventRecord(ev_setup, 0);

    // 2a) kNN on stream A
    cudaStreamWaitEvent(s_knn, ev_setup, 0);
    dim3 qgrid(NCELL, B_SZ);
    knn_query<<<qgrid, 128, 0, s_knn>>>(p_up);
    cudaEventRecord(ev_knn, s_knn);

    // 2b) down MLP -> g_xd on stream B
    cudaStreamWaitEvent(s_down, ev_setup, 0);
    gemm_mma<C_IN><<<M_DOWN / 128, 256, 0, s_down>>>(
        x_down, wdh, wdl, b_down, g_down, be_down, m_down, v_down, xd);
    cudaEventRecord(ev_down, s_down);

    // 2c) up MLP main (BN+ReLU -> out) on main stream — no kNN/down dependency
    gemm_mma<C_OUT><<<M_UP / 128, 256>>>(
        x_up, wuh, wul, b_up, g_up, be_up, m_up, v_up, out);

    // 3) join all, then gather + add
    cudaStreamWaitEvent(0, ev_knn, 0);
    cudaStreamWaitEvent(0, ev_down, 0);
    gather_add<<<M_UP / 8, 256>>>(out);
}